// round 2
// baseline (speedup 1.0000x reference)
#include <cuda_runtime.h>
#include <math.h>

#define B   2
#define L   2048
#define EMB 2048
#define NH  16
#define HD  128

// ---------------- scratch (device globals: no allocation allowed) -------------
__device__ float g_Q[2 * 16 * 2048 * 128];   // [B][NH][L][HD], RoPE'd
__device__ float g_K[2 * 2048 * 128];        // [B][L][HD],    RoPE'd
__device__ float g_V[2 * 2048 * 128];        // [B][L][HD]
__device__ float g_Rc[2048 * 64];            // cos table [L][HD/2]
__device__ float g_Rs[2048 * 64];            // sin table

// ---------------- RoPE tables (double precision, one-time tiny cost) ----------
__global__ void rope_table_kernel() {
    int idx = blockIdx.x * blockDim.x + threadIdx.x;   // 2048*64 threads exactly
    int l = idx >> 6;
    int i = idx & 63;
    double invf = pow(10000.0, -(double)(2 * i) / (double)HD);
    double a = (double)l * invf;
    g_Rc[idx] = (float)cos(a);
    g_Rs[idx] = (float)sin(a);
}

// ---------------- fused QKV projection GEMM with RoPE epilogue ----------------
// Grid: x = 18 column blocks (0..15 -> Wq cols, 16 -> Wk, 17 -> Wv), y = 32 row blocks.
// BM=128, BN=128, BK=16, 256 threads, 8x8 register microtile.
__global__ __launch_bounds__(256) void qkv_gemm_kernel(
    const float* __restrict__ X,  const float* __restrict__ Wq,
    const float* __restrict__ Wk, const float* __restrict__ Wv) {
    __shared__ float As[16][128];   // A transposed: As[k][m]
    __shared__ float Bs[16][128];   // Bs[k][n]

    int t = threadIdx.x;
    int tx = t & 15, ty = t >> 4;
    int bx = blockIdx.x;
    int m0 = blockIdx.y * 128;

    const float* Wp;
    int ldw, mode;
    if (bx < 16)       { Wp = Wq; ldw = NH * HD; mode = 0; }
    else if (bx == 16) { Wp = Wk; ldw = HD;      mode = 1; }
    else               { Wp = Wv; ldw = HD;      mode = 2; }
    int nbase = (mode == 0) ? bx * 128 : 0;

    float acc[8][8];
#pragma unroll
    for (int i = 0; i < 8; i++)
#pragma unroll
        for (int j = 0; j < 8; j++) acc[i][j] = 0.f;

    for (int k0 = 0; k0 < EMB; k0 += 16) {
#pragma unroll
        for (int i = 0; i < 2; i++) {          // A tile: 128 rows x 16 k
            int f = t * 2 + i;
            int row = f >> 2, kc = (f & 3) * 4;
            float4 v = *(const float4*)(X + (size_t)(m0 + row) * EMB + k0 + kc);
            As[kc    ][row] = v.x;
            As[kc + 1][row] = v.y;
            As[kc + 2][row] = v.z;
            As[kc + 3][row] = v.w;
        }
#pragma unroll
        for (int i = 0; i < 2; i++) {          // B tile: 16 k x 128 n
            int f = t * 2 + i;
            int kr = f >> 5, nc = (f & 31) * 4;
            *(float4*)&Bs[kr][nc] =
                *(const float4*)(Wp + (size_t)(k0 + kr) * ldw + nbase + nc);
        }
        __syncthreads();
#pragma unroll
        for (int k = 0; k < 16; k++) {
            float a[8], b[8];
            *(float4*)&a[0] = *(const float4*)&As[k][ty * 8];
            *(float4*)&a[4] = *(const float4*)&As[k][ty * 8 + 4];
            *(float4*)&b[0] = *(const float4*)&Bs[k][tx * 8];
            *(float4*)&b[4] = *(const float4*)&Bs[k][tx * 8 + 4];
#pragma unroll
            for (int i = 0; i < 8; i++)
#pragma unroll
                for (int j = 0; j < 8; j++) acc[i][j] += a[i] * b[j];
        }
        __syncthreads();
    }

    // epilogue: RoPE (Q,K) + scatter to scratch layouts
#pragma unroll
    for (int i = 0; i < 8; i++) {
        int m = m0 + ty * 8 + i;
        int bb = m >> 11;         // m / L
        int l  = m & 2047;        // m % L
        float r[8];
        if (mode == 2) {
#pragma unroll
            for (int j = 0; j < 8; j++) r[j] = acc[i][j];
            float* dst = g_V + (size_t)m * HD + tx * 8;
            *(float4*)dst       = make_float4(r[0], r[1], r[2], r[3]);
            *(float4*)(dst + 4) = make_float4(r[4], r[5], r[6], r[7]);
        } else {
            int d0 = tx * 8;      // head-local dim base (cols within a 128-block)
#pragma unroll
            for (int j = 0; j < 8; j += 2) {
                int dd = d0 + j;
                float c = g_Rc[l * 64 + (dd >> 1)];
                float s = g_Rs[l * 64 + (dd >> 1)];
                float e = acc[i][j], o = acc[i][j + 1];
                r[j]     = e * c - o * s;
                r[j + 1] = o * c + e * s;
            }
            float* dst;
            if (mode == 0) {
                int n = nbase + tx * 8;
                int h = n >> 7, d = n & 127;
                dst = g_Q + (((size_t)(bb * NH + h) * L + l) * HD + d);
            } else {
                dst = g_K + (size_t)m * HD + tx * 8;
            }
            *(float4*)dst       = make_float4(r[0], r[1], r[2], r[3]);
            *(float4*)(dst + 4) = make_float4(r[4], r[5], r[6], r[7]);
        }
    }
}

// ---------------- causal flash attention ---------------------------------------
// Grid (16 qtiles, 16 heads, 2 batch), 256 threads.
// BQ=128 rows per block, BKT=64 K/V cols per iteration, D=128.
// smem: Qt[d][q] 128x132, Kt[d][c] 128x68, V[c][d] 64x132, P[q][c] 128x68 -> 167KB
#define SQ(d, q) sQ[(d) * 132 + (q)]
#define SK(d, c) sK[(d) * 68 + (c)]
#define SV(c, d) sV[(c) * 132 + (d)]
#define SP(q, c) sP[(q) * 68 + (c)]

__global__ __launch_bounds__(256, 1) void attn_kernel(float* __restrict__ out) {
    extern __shared__ float smem[];
    float* sQ = smem;               // 16896 floats
    float* sK = smem + 16896;       // 8704
    float* sV = smem + 25600;       // 8448
    float* sP = smem + 34048;       // 8704  (total 42752 floats = 171008 B)

    int t = threadIdx.x;
    int tx = t & 15, ty = t >> 4;
    int qt = blockIdx.x, h = blockIdx.y, b = blockIdx.z;
    int q0 = qt * 128;

    const float* Qp = g_Q + ((size_t)(b * NH + h) * L + q0) * HD;
    const float* Kp = g_K + (size_t)b * L * HD;
    const float* Vp = g_V + (size_t)b * L * HD;

    // load Q tile transposed: conflict-free STS (lanes cover consecutive q rows)
    {
        int qrow = t & 127;
        int dg = (t >> 7) * 4;
#pragma unroll
        for (int it = 0; it < 16; it++) {
            int d = dg + 8 * it;
            float4 v = *(const float4*)(Qp + (size_t)qrow * HD + d);
            SQ(d,     qrow) = v.x;
            SQ(d + 1, qrow) = v.y;
            SQ(d + 2, qrow) = v.z;
            SQ(d + 3, qrow) = v.w;
        }
    }

    float o[8][8];
    float mrow[8], lrow[8];
#pragma unroll
    for (int i = 0; i < 8; i++) {
        mrow[i] = -INFINITY;
        lrow[i] = 0.f;
#pragma unroll
        for (int j = 0; j < 8; j++) o[i][j] = 0.f;
    }

    const float scale = 0.08838834764831845f;   // 1/sqrt(128)
    int jmax = q0 + 128;                        // causal bound (<= L)

    for (int j0 = 0; j0 < jmax; j0 += 64) {
        __syncthreads();
        // K tile transposed (lanes cover consecutive kc -> conflict-free STS)
        {
            int kc = t & 63, dgk = (t >> 6) * 4;
#pragma unroll
            for (int it = 0; it < 8; it++) {
                int d = dgk + 16 * it;
                float4 v = *(const float4*)(Kp + (size_t)(j0 + kc) * HD + d);
                SK(d,     kc) = v.x;
                SK(d + 1, kc) = v.y;
                SK(d + 2, kc) = v.z;
                SK(d + 3, kc) = v.w;
            }
        }
        // V tile natural layout, fully coalesced
        {
#pragma unroll
            for (int it = 0; it < 8; it++) {
                int f = t + 256 * it;
                int r = f >> 5, dc = (f & 31) * 4;
                *(float4*)&SV(r, dc) =
                    *(const float4*)(Vp + (size_t)(j0 + r) * HD + dc);
            }
        }
        __syncthreads();

        // S = Q K^T  (128x64 tile, 8x4 per thread, k = head dim)
        float sacc[8][4];
#pragma unroll
        for (int i = 0; i < 8; i++)
#pragma unroll
            for (int j = 0; j < 4; j++) sacc[i][j] = 0.f;
#pragma unroll 8
        for (int k = 0; k < 128; k++) {
            float a[8], bb[4];
            *(float4*)&a[0]  = *(const float4*)&SQ(k, ty * 8);
            *(float4*)&a[4]  = *(const float4*)&SQ(k, ty * 8 + 4);
            *(float4*)&bb[0] = *(const float4*)&SK(k, tx * 4);
#pragma unroll
            for (int i = 0; i < 8; i++)
#pragma unroll
                for (int j = 0; j < 4; j++) sacc[i][j] += a[i] * bb[j];
        }

        // online softmax (row reductions via shuffle over tx = lane bits 0..3)
#pragma unroll
        for (int i = 0; i < 8; i++) {
            int grow = q0 + ty * 8 + i;
            float rmax = -INFINITY;
#pragma unroll
            for (int j = 0; j < 4; j++) {
                int gcol = j0 + tx * 4 + j;
                float s = (gcol <= grow) ? sacc[i][j] * scale : -INFINITY;
                sacc[i][j] = s;
                rmax = fmaxf(rmax, s);
            }
            rmax = fmaxf(rmax, __shfl_xor_sync(0xffffffffu, rmax, 1));
            rmax = fmaxf(rmax, __shfl_xor_sync(0xffffffffu, rmax, 2));
            rmax = fmaxf(rmax, __shfl_xor_sync(0xffffffffu, rmax, 4));
            rmax = fmaxf(rmax, __shfl_xor_sync(0xffffffffu, rmax, 8));
            float mnew = fmaxf(mrow[i], rmax);
            float corr = expf(mrow[i] - mnew);
            float rsum = 0.f;
#pragma unroll
            for (int j = 0; j < 4; j++) {
                float p = expf(sacc[i][j] - mnew);
                sacc[i][j] = p;
                rsum += p;
            }
            rsum += __shfl_xor_sync(0xffffffffu, rsum, 1);
            rsum += __shfl_xor_sync(0xffffffffu, rsum, 2);
            rsum += __shfl_xor_sync(0xffffffffu, rsum, 4);
            rsum += __shfl_xor_sync(0xffffffffu, rsum, 8);
            lrow[i] = lrow[i] * corr + rsum;
            mrow[i] = mnew;
#pragma unroll
            for (int j = 0; j < 8; j++) o[i][j] *= corr;
#pragma unroll
            for (int j = 0; j < 4; j++) SP(ty * 8 + i, tx * 4 + j) = sacc[i][j];
        }
        __syncthreads();

        // O += P V  (128x128 tile, 8x8 per thread, k = kv col)
#pragma unroll 4
        for (int kc = 0; kc < 64; kc++) {
            float a[8], bb[8];
#pragma unroll
            for (int i = 0; i < 8; i++) a[i] = SP(ty * 8 + i, kc);
            *(float4*)&bb[0] = *(const float4*)&SV(kc, tx * 8);
            *(float4*)&bb[4] = *(const float4*)&SV(kc, tx * 8 + 4);
#pragma unroll
            for (int i = 0; i < 8; i++)
#pragma unroll
                for (int j = 0; j < 8; j++) o[i][j] += a[i] * bb[j];
        }
    }

    // epilogue: normalize + write [B, L, NH*HD]
#pragma unroll
    for (int i = 0; i < 8; i++) {
        float inv = 1.f / lrow[i];
        int row = q0 + ty * 8 + i;
        float* dst = out + (size_t)(b * L + row) * (NH * HD) + h * HD + tx * 8;
        *(float4*)dst =
            make_float4(o[i][0] * inv, o[i][1] * inv, o[i][2] * inv, o[i][3] * inv);
        *(float4*)(dst + 4) =
            make_float4(o[i][4] * inv, o[i][5] * inv, o[i][6] * inv, o[i][7] * inv);
    }
}

// ---------------- launch --------------------------------------------------------
extern "C" void kernel_launch(void* const* d_in, const int* in_sizes, int n_in,
                              void* d_out, int out_size) {
    const float* x  = (const float*)d_in[0];
    const float* Wq = (const float*)d_in[1];
    const float* Wk = (const float*)d_in[2];
    const float* Wv = (const float*)d_in[3];
    float* out = (float*)d_out;

    (void)cudaFuncSetAttribute(attn_kernel,
                               cudaFuncAttributeMaxDynamicSharedMemorySize, 171008);

    rope_table_kernel<<<512, 256>>>();
    qkv_gemm_kernel<<<dim3(18, 32), 256>>>(x, Wq, Wk, Wv);
    attn_kernel<<<dim3(16, NH, B), 256, 171008>>>(out);
}

// round 5
// speedup vs baseline: 1.3076x; 1.3076x over previous
#include <cuda_runtime.h>
#include <cuda_bf16.h>
#include <math.h>
#include <stdint.h>

#define B   2
#define L   2048
#define EMB 2048
#define NH  16
#define HD  128
#define NTOT 2304          // 2048 Q cols + 128 K + 128 V

// ---------------- scratch (device globals: no allocation allowed) -------------
__device__ float g_Q[2 * 16 * 2048 * 128];        // [B][NH][L][HD], RoPE'd
__device__ float g_K[2 * 2048 * 128];             // [B][L][HD],    RoPE'd
__device__ float g_V[2 * 2048 * 128];             // [B][L][HD]
__device__ float g_Rc[2048 * 64];                 // cos table [L][HD/2]
__device__ float g_Rs[2048 * 64];                 // sin table
__device__ __nv_bfloat16 g_Xh[4096 * 2048];       // X split hi (bf16)
__device__ __nv_bfloat16 g_Xl[4096 * 2048];       // X split lo
__device__ __nv_bfloat16 g_Wth[NTOT * 2048];      // W^T split hi  [n][k]
__device__ __nv_bfloat16 g_Wtl[NTOT * 2048];      // W^T split lo

// ---------------- PTX helpers ---------------------------------------------------
__device__ __forceinline__ uint32_t smem_u32(const void* p) {
    uint32_t a;
    asm("{ .reg .u64 t; cvta.to.shared.u64 t, %1; cvt.u32.u64 %0, t; }" : "=r"(a) : "l"(p));
    return a;
}
__device__ __forceinline__ void cpa16(uint32_t dst, const void* src) {
    asm volatile("cp.async.cg.shared.global [%0], [%1], 16;" :: "r"(dst), "l"(src));
}
#define CPA_COMMIT() asm volatile("cp.async.commit_group;" ::: "memory")
#define CPA_WAIT0()  asm volatile("cp.async.wait_group 0;" ::: "memory")
#define CPA_WAIT1()  asm volatile("cp.async.wait_group 1;" ::: "memory")

__device__ __forceinline__ void ldm_x4(uint32_t* r, uint32_t addr) {
    asm volatile("ldmatrix.sync.aligned.m8n8.x4.shared.b16 {%0,%1,%2,%3}, [%4];"
        : "=r"(r[0]), "=r"(r[1]), "=r"(r[2]), "=r"(r[3]) : "r"(addr));
}
__device__ __forceinline__ void mma_bf16(float* c, const uint32_t* a, const uint32_t* b) {
    asm volatile("mma.sync.aligned.m16n8k16.row.col.f32.bf16.bf16.f32 "
        "{%0,%1,%2,%3}, {%4,%5,%6,%7}, {%8,%9}, {%0,%1,%2,%3};"
        : "+f"(c[0]), "+f"(c[1]), "+f"(c[2]), "+f"(c[3])
        : "r"(a[0]), "r"(a[1]), "r"(a[2]), "r"(a[3]), "r"(b[0]), "r"(b[1]));
}

// ---------------- RoPE tables ----------------------------------------------------
__global__ void rope_table_kernel() {
    int idx = blockIdx.x * blockDim.x + threadIdx.x;
    int l = idx >> 6;
    int i = idx & 63;
    double invf = pow(10000.0, -(double)(2 * i) / (double)HD);
    double a = (double)l * invf;
    g_Rc[idx] = (float)cos(a);
    g_Rs[idx] = (float)sin(a);
}

// ---------------- X hi/lo bf16 split --------------------------------------------
__global__ void xsplit_kernel(const float* __restrict__ X) {
    int i = (blockIdx.x * 256 + threadIdx.x) * 4;
    float4 v = *(const float4*)(X + i);
    __nv_bfloat16 h[4], lo[4];
    float vv[4] = {v.x, v.y, v.z, v.w};
#pragma unroll
    for (int j = 0; j < 4; j++) {
        h[j]  = __float2bfloat16(vv[j]);
        lo[j] = __float2bfloat16(vv[j] - __bfloat162float(h[j]));
    }
    *(uint2*)(g_Xh + i) = *(uint2*)h;
    *(uint2*)(g_Xl + i) = *(uint2*)lo;
}

// ---------------- W transpose + hi/lo bf16 split --------------------------------
__global__ void wsplit_kernel(const float* __restrict__ Wq,
                              const float* __restrict__ Wk,
                              const float* __restrict__ Wv) {
    __shared__ float tile[32][33];
    int kb = blockIdx.x * 32;
    int nb = blockIdx.y * 32;
    const float* W; int ldw, n0;
    if (nb < 2048)      { W = Wq; ldw = 2048; n0 = nb; }
    else if (nb < 2176) { W = Wk; ldw = 128;  n0 = nb - 2048; }
    else                { W = Wv; ldw = 128;  n0 = nb - 2176; }
    int tx = threadIdx.x & 31, ty = threadIdx.x >> 5;    // 256 threads
#pragma unroll
    for (int r = 0; r < 32; r += 8)
        tile[ty + r][tx] = W[(size_t)(kb + ty + r) * ldw + n0 + tx];
    __syncthreads();
#pragma unroll
    for (int r = 0; r < 32; r += 8) {
        float v = tile[tx][ty + r];
        __nv_bfloat16 h = __float2bfloat16(v);
        __nv_bfloat16 lo = __float2bfloat16(v - __bfloat162float(h));
        size_t o = (size_t)(nb + ty + r) * 2048 + kb + tx;
        g_Wth[o] = h;
        g_Wtl[o] = lo;
    }
}

// ---------------- QKV GEMM: split-bf16 mma.sync, RoPE epilogue ------------------
// Grid (18 nblocks, 32 mblocks), 256 threads = 8 warps (4 m x 2 n).
// Block tile 128x128, warp tile 32x64, BK=32. smem rows padded to 80B
// (bank starts (20*r)%32 disjoint -> conflict-free ldmatrix).
#define TS      80                  // bytes per smem tile row
#define TILE_B  (128 * TS)          // 10240
#define STG_B   (4 * TILE_B)        // 40960: Ah | Al | Bh | Bl
#define NCHUNK  64

__device__ __forceinline__ void load_chunk(uint32_t sbase, int stage,
                                           int m0, int n0, int kc, int t) {
    uint32_t sb = sbase + stage * STG_B;
#pragma unroll
    for (int it = 0; it < 8; it++) {
        int g = t + 256 * it;               // 0..2047
        int tile = g >> 9;
        int r = (g >> 2) & 127;
        int c = g & 3;
        uint32_t dst = sb + tile * TILE_B + r * TS + c * 16;
        const __nv_bfloat16* src;
        if (tile == 0)      src = g_Xh  + (size_t)(m0 + r) * EMB + kc + c * 8;
        else if (tile == 1) src = g_Xl  + (size_t)(m0 + r) * EMB + kc + c * 8;
        else if (tile == 2) src = g_Wth + (size_t)(n0 + r) * EMB + kc + c * 8;
        else                src = g_Wtl + (size_t)(n0 + r) * EMB + kc + c * 8;
        cpa16(dst, src);
    }
}

__global__ __launch_bounds__(256, 1) void qkv_gemm_kernel() {
    extern __shared__ char smem[];
    uint32_t sbase = smem_u32(smem);
    int t = threadIdx.x;
    int lane = t & 31, w = t >> 5;
    int wm = w & 3, wn = w >> 2;
    int nb = blockIdx.x;
    int m0 = blockIdx.y * 128;
    int n0 = nb * 128;

    float acc[2][8][4];
#pragma unroll
    for (int i = 0; i < 2; i++)
#pragma unroll
        for (int j = 0; j < 8; j++)
#pragma unroll
            for (int q = 0; q < 4; q++) acc[i][j][q] = 0.f;

    // ldmatrix per-thread offsets
    int aRow = wm * 32 + (lane & 15);            // + mf*16
    uint32_t aOff = (uint32_t)(aRow * TS + ((lane >> 4) << 4));
    int bRow = wn * 64 + ((lane >> 4) << 3) + (lane & 7);   // + ng*16
    uint32_t bOff = (uint32_t)(bRow * TS + (((lane >> 3) & 1) << 4));

    load_chunk(sbase, 0, m0, n0, 0, t);
    CPA_COMMIT();

    for (int i = 0; i < NCHUNK; i++) {
        int s = i & 1;
        if (i + 1 < NCHUNK) {
            load_chunk(sbase, s ^ 1, m0, n0, (i + 1) * 32, t);
            CPA_COMMIT();
            CPA_WAIT1();
        } else {
            CPA_WAIT0();
        }
        __syncthreads();

        uint32_t sb = sbase + s * STG_B;
#pragma unroll
        for (int ks = 0; ks < 2; ks++) {
            uint32_t kb = ks * 32;               // 16 bf16 = 32 bytes
            uint32_t ah[2][4], al[2][4];
#pragma unroll
            for (int mf = 0; mf < 2; mf++) {
                ldm_x4(ah[mf], sb + aOff + (uint32_t)(mf * 16 * TS) + kb);
                ldm_x4(al[mf], sb + TILE_B + aOff + (uint32_t)(mf * 16 * TS) + kb);
            }
#pragma unroll
            for (int ng = 0; ng < 4; ng++) {
                uint32_t bh[4], bl[4];
                uint32_t bo = bOff + (uint32_t)(ng * 16 * TS) + kb;
                ldm_x4(bh, sb + 2 * TILE_B + bo);
                ldm_x4(bl, sb + 3 * TILE_B + bo);
#pragma unroll
                for (int sub = 0; sub < 2; sub++) {
                    int nf = ng * 2 + sub;
                    mma_bf16(acc[0][nf], ah[0], bh + 2 * sub);
                    mma_bf16(acc[1][nf], ah[1], bh + 2 * sub);
                    mma_bf16(acc[0][nf], ah[0], bl + 2 * sub);
                    mma_bf16(acc[1][nf], ah[1], bl + 2 * sub);
                    mma_bf16(acc[0][nf], al[0], bh + 2 * sub);
                    mma_bf16(acc[1][nf], al[1], bh + 2 * sub);
                }
            }
        }
        __syncthreads();
    }

    // epilogue: RoPE (Q,K) + scatter. acc cols 2*(lane%4), +1 = RoPE pair.
#pragma unroll
    for (int mf = 0; mf < 2; mf++) {
#pragma unroll
        for (int half = 0; half < 2; half++) {      // c0,c1 row r; c2,c3 row r+8
            int row = m0 + wm * 32 + mf * 16 + (lane >> 2) + half * 8;
            int bb = row >> 11;
            int l  = row & 2047;
#pragma unroll
            for (int nf = 0; nf < 8; nf++) {
                int dcol = wn * 64 + nf * 8 + ((lane & 3) << 1);   // 0..127
                float e = acc[mf][nf][half * 2 + 0];
                float o = acc[mf][nf][half * 2 + 1];
                float2 v;
                if (nb != 17) {
                    float c  = g_Rc[l * 64 + (dcol >> 1)];
                    float sn = g_Rs[l * 64 + (dcol >> 1)];
                    v.x = e * c - o * sn;
                    v.y = o * c + e * sn;
                } else {
                    v.x = e; v.y = o;
                }
                float* dst;
                if (nb < 16)
                    dst = g_Q + ((size_t)(bb * NH + nb) * L + l) * HD + dcol;
                else if (nb == 16)
                    dst = g_K + (size_t)row * HD + dcol;
                else
                    dst = g_V + (size_t)row * HD + dcol;
                *(float2*)dst = v;
            }
        }
    }
}

// ---------------- causal flash attention (unchanged, known-good) ----------------
#define SQ(d, q) sQ[(d) * 132 + (q)]
#define SK(d, c) sK[(d) * 68 + (c)]
#define SV(c, d) sV[(c) * 132 + (d)]
#define SP(q, c) sP[(q) * 68 + (c)]

__global__ __launch_bounds__(256, 1) void attn_kernel(float* __restrict__ out) {
    extern __shared__ float smemf[];
    float* sQ = smemf;
    float* sK = smemf + 16896;
    float* sV = smemf + 25600;
    float* sP = smemf + 34048;

    int t = threadIdx.x;
    int tx = t & 15, ty = t >> 4;
    int qt = blockIdx.x, h = blockIdx.y, b = blockIdx.z;
    int q0 = qt * 128;

    const float* Qp = g_Q + ((size_t)(b * NH + h) * L + q0) * HD;
    const float* Kp = g_K + (size_t)b * L * HD;
    const float* Vp = g_V + (size_t)b * L * HD;

    {
        int qrow = t & 127;
        int dg = (t >> 7) * 4;
#pragma unroll
        for (int it = 0; it < 16; it++) {
            int d = dg + 8 * it;
            float4 v = *(const float4*)(Qp + (size_t)qrow * HD + d);
            SQ(d,     qrow) = v.x;
            SQ(d + 1, qrow) = v.y;
            SQ(d + 2, qrow) = v.z;
            SQ(d + 3, qrow) = v.w;
        }
    }

    float o[8][8];
    float mrow[8], lrow[8];
#pragma unroll
    for (int i = 0; i < 8; i++) {
        mrow[i] = -INFINITY;
        lrow[i] = 0.f;
#pragma unroll
        for (int j = 0; j < 8; j++) o[i][j] = 0.f;
    }

    const float scale = 0.08838834764831845f;
    int jmax = q0 + 128;

    for (int j0 = 0; j0 < jmax; j0 += 64) {
        __syncthreads();
        {
            int kc = t & 63, dgk = (t >> 6) * 4;
#pragma unroll
            for (int it = 0; it < 8; it++) {
                int d = dgk + 16 * it;
                float4 v = *(const float4*)(Kp + (size_t)(j0 + kc) * HD + d);
                SK(d,     kc) = v.x;
                SK(d + 1, kc) = v.y;
                SK(d + 2, kc) = v.z;
                SK(d + 3, kc) = v.w;
            }
        }
        {
#pragma unroll
            for (int it = 0; it < 8; it++) {
                int f = t + 256 * it;
                int r = f >> 5, dc = (f & 31) * 4;
                *(float4*)&SV(r, dc) =
                    *(const float4*)(Vp + (size_t)(j0 + r) * HD + dc);
            }
        }
        __syncthreads();

        float sacc[8][4];
#pragma unroll
        for (int i = 0; i < 8; i++)
#pragma unroll
            for (int j = 0; j < 4; j++) sacc[i][j] = 0.f;
#pragma unroll 8
        for (int k = 0; k < 128; k++) {
            float a[8], bb[4];
            *(float4*)&a[0]  = *(const float4*)&SQ(k, ty * 8);
            *(float4*)&a[4]  = *(const float4*)&SQ(k, ty * 8 + 4);
            *(float4*)&bb[0] = *(const float4*)&SK(k, tx * 4);
#pragma unroll
            for (int i = 0; i < 8; i++)
#pragma unroll
                for (int j = 0; j < 4; j++) sacc[i][j] += a[i] * bb[j];
        }

#pragma unroll
        for (int i = 0; i < 8; i++) {
            int grow = q0 + ty * 8 + i;
            float rmax = -INFINITY;
#pragma unroll
            for (int j = 0; j < 4; j++) {
                int gcol = j0 + tx * 4 + j;
                float s = (gcol <= grow) ? sacc[i][j] * scale : -INFINITY;
                sacc[i][j] = s;
                rmax = fmaxf(rmax, s);
            }
            rmax = fmaxf(rmax, __shfl_xor_sync(0xffffffffu, rmax, 1));
            rmax = fmaxf(rmax, __shfl_xor_sync(0xffffffffu, rmax, 2));
            rmax = fmaxf(rmax, __shfl_xor_sync(0xffffffffu, rmax, 4));
            rmax = fmaxf(rmax, __shfl_xor_sync(0xffffffffu, rmax, 8));
            float mnew = fmaxf(mrow[i], rmax);
            float corr = expf(mrow[i] - mnew);
            float rsum = 0.f;
#pragma unroll
            for (int j = 0; j < 4; j++) {
                float p = expf(sacc[i][j] - mnew);
                sacc[i][j] = p;
                rsum += p;
            }
            rsum += __shfl_xor_sync(0xffffffffu, rsum, 1);
            rsum += __shfl_xor_sync(0xffffffffu, rsum, 2);
            rsum += __shfl_xor_sync(0xffffffffu, rsum, 4);
            rsum += __shfl_xor_sync(0xffffffffu, rsum, 8);
            lrow[i] = lrow[i] * corr + rsum;
            mrow[i] = mnew;
#pragma unroll
            for (int j = 0; j < 8; j++) o[i][j] *= corr;
#pragma unroll
            for (int j = 0; j < 4; j++) SP(ty * 8 + i, tx * 4 + j) = sacc[i][j];
        }
        __syncthreads();

#pragma unroll 4
        for (int kc = 0; kc < 64; kc++) {
            float a[8], bb[8];
#pragma unroll
            for (int i = 0; i < 8; i++) a[i] = SP(ty * 8 + i, kc);
            *(float4*)&bb[0] = *(const float4*)&SV(kc, tx * 8);
            *(float4*)&bb[4] = *(const float4*)&SV(kc, tx * 8 + 4);
#pragma unroll
            for (int i = 0; i < 8; i++)
#pragma unroll
                for (int j = 0; j < 8; j++) o[i][j] += a[i] * bb[j];
        }
    }

#pragma unroll
    for (int i = 0; i < 8; i++) {
        float inv = 1.f / lrow[i];
        int row = q0 + ty * 8 + i;
        float* dst = out + (size_t)(b * L + row) * (NH * HD) + h * HD + tx * 8;
        *(float4*)dst =
            make_float4(o[i][0] * inv, o[i][1] * inv, o[i][2] * inv, o[i][3] * inv);
        *(float4*)(dst + 4) =
            make_float4(o[i][4] * inv, o[i][5] * inv, o[i][6] * inv, o[i][7] * inv);
    }
}

// ---------------- launch --------------------------------------------------------
extern "C" void kernel_launch(void* const* d_in, const int* in_sizes, int n_in,
                              void* d_out, int out_size) {
    const float* x  = (const float*)d_in[0];
    const float* Wq = (const float*)d_in[1];
    const float* Wk = (const float*)d_in[2];
    const float* Wv = (const float*)d_in[3];
    float* out = (float*)d_out;

    (void)cudaFuncSetAttribute(qkv_gemm_kernel,
                               cudaFuncAttributeMaxDynamicSharedMemorySize, 81920);
    (void)cudaFuncSetAttribute(attn_kernel,
                               cudaFuncAttributeMaxDynamicSharedMemorySize, 171008);

    rope_table_kernel<<<512, 256>>>();
    xsplit_kernel<<<8192, 256>>>(x);
    wsplit_kernel<<<dim3(64, 72), 256>>>(Wq, Wk, Wv);
    qkv_gemm_kernel<<<dim3(18, 32), 256, 81920>>>();
    attn_kernel<<<dim3(16, NH, B), 256, 171008>>>(out);
}

// round 6
// speedup vs baseline: 3.0563x; 2.3373x over previous
#include <cuda_runtime.h>
#include <cuda_fp16.h>
#include <math.h>
#include <stdint.h>

#define B   2
#define L   2048
#define EMB 2048
#define NH  16
#define HD  128
#define NTOT 2304          // 2048 Q cols + 128 K + 128 V

// ---------------- scratch (device globals: no allocation allowed) -------------
__device__ __half g_Qh[2 * 16 * 2048 * 128];  // [B][NH][L][HD] RoPE'd, fp16 hi
__device__ __half g_Ql[2 * 16 * 2048 * 128];  // fp16 lo
__device__ __half g_Kh[2 * 2048 * 128];       // [B][L][HD] RoPE'd
__device__ __half g_Kl[2 * 2048 * 128];
__device__ __half g_Vh[2 * 2048 * 128];
__device__ __half g_Vl[2 * 2048 * 128];
__device__ float  g_Rc[2048 * 64];
__device__ float  g_Rs[2048 * 64];
__device__ __half g_Xh[4096 * 2048];          // X split hi
__device__ __half g_Xl[4096 * 2048];          // X split lo
__device__ __half g_Wth[NTOT * 2048];         // W^T split hi [n][k]
__device__ __half g_Wtl[NTOT * 2048];

// ---------------- PTX helpers ---------------------------------------------------
__device__ __forceinline__ uint32_t smem_u32(const void* p) {
    uint32_t a;
    asm("{ .reg .u64 t; cvta.to.shared.u64 t, %1; cvt.u32.u64 %0, t; }" : "=r"(a) : "l"(p));
    return a;
}
__device__ __forceinline__ void cpa16(uint32_t dst, const void* src) {
    asm volatile("cp.async.cg.shared.global [%0], [%1], 16;" :: "r"(dst), "l"(src));
}
#define CPA_COMMIT() asm volatile("cp.async.commit_group;" ::: "memory")
#define CPA_WAIT0()  asm volatile("cp.async.wait_group 0;" ::: "memory")
#define CPA_WAIT1()  asm volatile("cp.async.wait_group 1;" ::: "memory")

__device__ __forceinline__ void ldm_x4(uint32_t* r, uint32_t addr) {
    asm volatile("ldmatrix.sync.aligned.m8n8.x4.shared.b16 {%0,%1,%2,%3}, [%4];"
        : "=r"(r[0]), "=r"(r[1]), "=r"(r[2]), "=r"(r[3]) : "r"(addr));
}
__device__ __forceinline__ void ldm_x4_t(uint32_t* r, uint32_t addr) {
    asm volatile("ldmatrix.sync.aligned.m8n8.x4.trans.shared.b16 {%0,%1,%2,%3}, [%4];"
        : "=r"(r[0]), "=r"(r[1]), "=r"(r[2]), "=r"(r[3]) : "r"(addr));
}
__device__ __forceinline__ void mma_f16(float* c, const uint32_t* a, const uint32_t* b) {
    asm volatile("mma.sync.aligned.m16n8k16.row.col.f32.f16.f16.f32 "
        "{%0,%1,%2,%3}, {%4,%5,%6,%7}, {%8,%9}, {%0,%1,%2,%3};"
        : "+f"(c[0]), "+f"(c[1]), "+f"(c[2]), "+f"(c[3])
        : "r"(a[0]), "r"(a[1]), "r"(a[2]), "r"(a[3]), "r"(b[0]), "r"(b[1]));
}
__device__ __forceinline__ uint32_t packh2(float a, float b) {
    __half2 h = __floats2half2_rn(a, b);
    return *(uint32_t*)&h;
}

// ---------------- RoPE tables ----------------------------------------------------
__global__ void rope_table_kernel() {
    int idx = blockIdx.x * blockDim.x + threadIdx.x;
    int l = idx >> 6;
    int i = idx & 63;
    double invf = pow(10000.0, -(double)(2 * i) / (double)HD);
    double a = (double)l * invf;
    g_Rc[idx] = (float)cos(a);
    g_Rs[idx] = (float)sin(a);
}

// ---------------- X hi/lo fp16 split --------------------------------------------
__global__ void xsplit_kernel(const float* __restrict__ X) {
    int i = (blockIdx.x * 256 + threadIdx.x) * 4;
    float4 v = *(const float4*)(X + i);
    float vv[4] = {v.x, v.y, v.z, v.w};
    __half h[4], lo[4];
#pragma unroll
    for (int j = 0; j < 4; j++) {
        h[j]  = __float2half_rn(vv[j]);
        lo[j] = __float2half_rn(vv[j] - __half2float(h[j]));
    }
    *(uint2*)(g_Xh + i) = *(uint2*)h;
    *(uint2*)(g_Xl + i) = *(uint2*)lo;
}

// ---------------- W transpose + hi/lo fp16 split --------------------------------
__global__ void wsplit_kernel(const float* __restrict__ Wq,
                              const float* __restrict__ Wk,
                              const float* __restrict__ Wv) {
    __shared__ float tile[32][33];
    int kb = blockIdx.x * 32;
    int nb = blockIdx.y * 32;
    const float* W; int ldw, n0;
    if (nb < 2048)      { W = Wq; ldw = 2048; n0 = nb; }
    else if (nb < 2176) { W = Wk; ldw = 128;  n0 = nb - 2048; }
    else                { W = Wv; ldw = 128;  n0 = nb - 2176; }
    int tx = threadIdx.x & 31, ty = threadIdx.x >> 5;
#pragma unroll
    for (int r = 0; r < 32; r += 8)
        tile[ty + r][tx] = W[(size_t)(kb + ty + r) * ldw + n0 + tx];
    __syncthreads();
#pragma unroll
    for (int r = 0; r < 32; r += 8) {
        float v = tile[tx][ty + r];
        __half h = __float2half_rn(v);
        size_t o = (size_t)(nb + ty + r) * 2048 + kb + tx;
        g_Wth[o] = h;
        g_Wtl[o] = __float2half_rn(v - __half2float(h));
    }
}

// ---------------- QKV GEMM: split-fp16 mma.sync, RoPE epilogue ------------------
#define TS      80
#define TILE_B  (128 * TS)
#define STG_B   (4 * TILE_B)
#define NCHUNK  64

__device__ __forceinline__ void load_chunk(uint32_t sbase, int stage,
                                           int m0, int n0, int kc, int t) {
    uint32_t sb = sbase + stage * STG_B;
#pragma unroll
    for (int it = 0; it < 8; it++) {
        int g = t + 256 * it;
        int tile = g >> 9;
        int r = (g >> 2) & 127;
        int c = g & 3;
        uint32_t dst = sb + tile * TILE_B + r * TS + c * 16;
        const __half* src;
        if (tile == 0)      src = g_Xh  + (size_t)(m0 + r) * EMB + kc + c * 8;
        else if (tile == 1) src = g_Xl  + (size_t)(m0 + r) * EMB + kc + c * 8;
        else if (tile == 2) src = g_Wth + (size_t)(n0 + r) * EMB + kc + c * 8;
        else                src = g_Wtl + (size_t)(n0 + r) * EMB + kc + c * 8;
        cpa16(dst, src);
    }
}

__global__ __launch_bounds__(256, 2) void qkv_gemm_kernel() {
    extern __shared__ char smem[];
    uint32_t sbase = smem_u32(smem);
    int t = threadIdx.x;
    int lane = t & 31, w = t >> 5;
    int wm = w & 3, wn = w >> 2;
    int nb = blockIdx.x;
    int m0 = blockIdx.y * 128;
    int n0 = nb * 128;

    float acc[2][8][4];
#pragma unroll
    for (int i = 0; i < 2; i++)
#pragma unroll
        for (int j = 0; j < 8; j++)
#pragma unroll
            for (int q = 0; q < 4; q++) acc[i][j][q] = 0.f;

    int aRow = wm * 32 + (lane & 15);
    uint32_t aOff = (uint32_t)(aRow * TS + ((lane >> 4) << 4));
    int bRow = wn * 64 + ((lane >> 4) << 3) + (lane & 7);
    uint32_t bOff = (uint32_t)(bRow * TS + (((lane >> 3) & 1) << 4));

    load_chunk(sbase, 0, m0, n0, 0, t);
    CPA_COMMIT();

    for (int i = 0; i < NCHUNK; i++) {
        int s = i & 1;
        if (i + 1 < NCHUNK) {
            load_chunk(sbase, s ^ 1, m0, n0, (i + 1) * 32, t);
            CPA_COMMIT();
            CPA_WAIT1();
        } else {
            CPA_WAIT0();
        }
        __syncthreads();

        uint32_t sb = sbase + s * STG_B;
#pragma unroll
        for (int ks = 0; ks < 2; ks++) {
            uint32_t kb = ks * 32;
            uint32_t ah[2][4], al[2][4];
#pragma unroll
            for (int mf = 0; mf < 2; mf++) {
                ldm_x4(ah[mf], sb + aOff + (uint32_t)(mf * 16 * TS) + kb);
                ldm_x4(al[mf], sb + TILE_B + aOff + (uint32_t)(mf * 16 * TS) + kb);
            }
#pragma unroll
            for (int ng = 0; ng < 4; ng++) {
                uint32_t bh[4], bl[4];
                uint32_t bo = bOff + (uint32_t)(ng * 16 * TS) + kb;
                ldm_x4(bh, sb + 2 * TILE_B + bo);
                ldm_x4(bl, sb + 3 * TILE_B + bo);
#pragma unroll
                for (int sub = 0; sub < 2; sub++) {
                    int nf = ng * 2 + sub;
                    mma_f16(acc[0][nf], ah[0], bh + 2 * sub);
                    mma_f16(acc[1][nf], ah[1], bh + 2 * sub);
                    mma_f16(acc[0][nf], ah[0], bl + 2 * sub);
                    mma_f16(acc[1][nf], ah[1], bl + 2 * sub);
                    mma_f16(acc[0][nf], al[0], bh + 2 * sub);
                    mma_f16(acc[1][nf], al[1], bh + 2 * sub);
                }
            }
        }
        __syncthreads();
    }

    // epilogue: RoPE (Q,K) + fp16 hi/lo split scatter
#pragma unroll
    for (int mf = 0; mf < 2; mf++) {
#pragma unroll
        for (int half = 0; half < 2; half++) {
            int row = m0 + wm * 32 + mf * 16 + (lane >> 2) + half * 8;
            int bb = row >> 11;
            int l  = row & 2047;
#pragma unroll
            for (int nf = 0; nf < 8; nf++) {
                int dcol = wn * 64 + nf * 8 + ((lane & 3) << 1);
                float e = acc[mf][nf][half * 2 + 0];
                float o = acc[mf][nf][half * 2 + 1];
                float2 v;
                if (nb != 17) {
                    float c  = g_Rc[l * 64 + (dcol >> 1)];
                    float sn = g_Rs[l * 64 + (dcol >> 1)];
                    v.x = e * c - o * sn;
                    v.y = o * c + e * sn;
                } else {
                    v.x = e; v.y = o;
                }
                __half hx = __float2half_rn(v.x), hy = __float2half_rn(v.y);
                __half2 hp; hp.x = hx; hp.y = hy;
                __half2 lp;
                lp.x = __float2half_rn(v.x - __half2float(hx));
                lp.y = __float2half_rn(v.y - __half2float(hy));
                size_t idx;
                __half *dh, *dl;
                if (nb < 16) {
                    idx = ((size_t)(bb * NH + nb) * L + l) * HD + dcol;
                    dh = g_Qh; dl = g_Ql;
                } else if (nb == 16) {
                    idx = (size_t)row * HD + dcol;
                    dh = g_Kh; dl = g_Kl;
                } else {
                    idx = (size_t)row * HD + dcol;
                    dh = g_Vh; dl = g_Vl;
                }
                *(__half2*)(dh + idx) = hp;
                *(__half2*)(dl + idx) = lp;
            }
        }
    }
}

// ---------------- causal flash attention: fp16 mma.sync -------------------------
// Grid (16 qtiles, 16 h, 2 b), 256 thr = 8 warps, warp = 16 q-rows.
// smem: Qh|Ql (128x272B each) + 2 KV stages (Kh|Kl|Vh|Vl, 64x272B each) = 208896B
#define ROWB 272
#define QT_B 34816         // 128*272
#define KT_B 17408         // 64*272
#define STAGE0 69632

__device__ __forceinline__ void load_kv(uint32_t sb, int stage, int b, int j0, int t) {
    uint32_t base = sb + STAGE0 + stage * (4 * KT_B);
#pragma unroll
    for (int it = 0; it < 16; it++) {
        int g = t + 256 * it;             // 0..4095
        int tile = g >> 10;               // Kh,Kl,Vh,Vl
        int r = (g >> 4) & 63;
        int c = g & 15;
        const __half* src;
        size_t off = (size_t)(b * L + j0 + r) * HD + c * 8;
        if (tile == 0)      src = g_Kh + off;
        else if (tile == 1) src = g_Kl + off;
        else if (tile == 2) src = g_Vh + off;
        else                src = g_Vl + off;
        cpa16(base + tile * KT_B + r * ROWB + c * 16, src);
    }
}

__global__ __launch_bounds__(256, 1) void attn_kernel(float* __restrict__ out) {
    extern __shared__ char sm[];
    uint32_t sb = smem_u32(sm);
    int t = threadIdx.x;
    int lane = t & 31, wq = t >> 5;
    int qt = blockIdx.x, h = blockIdx.y, b = blockIdx.z;
    int q0 = qt * 128;

    // load Q hi/lo tiles
    {
        const __half* Qh = g_Qh + ((size_t)(b * NH + h) * L + q0) * HD;
        const __half* Ql = g_Ql + ((size_t)(b * NH + h) * L + q0) * HD;
#pragma unroll
        for (int it = 0; it < 16; it++) {
            int g = t + 256 * it;          // 0..4095
            int tile = g >> 11;
            int r = (g >> 4) & 127;
            int c = g & 15;
            const __half* src = (tile ? Ql : Qh) + (size_t)r * HD + c * 8;
            cpa16(sb + tile * QT_B + r * ROWB + c * 16, src);
        }
    }
    load_kv(sb, 0, b, 0, t);
    CPA_COMMIT();

    float o[16][4];
#pragma unroll
    for (int i = 0; i < 16; i++)
#pragma unroll
        for (int j = 0; j < 4; j++) o[i][j] = 0.f;
    float m1 = -INFINITY, m2 = -INFINITY, l1 = 0.f, l2 = 0.f;

    const float scale = 0.08838834764831845f;
    int niter = 2 * qt + 2;
    int grow1 = q0 + wq * 16 + (lane >> 2);
    int grow2 = grow1 + 8;

    uint32_t aoff  = (uint32_t)((wq * 16 + (lane & 15)) * ROWB + ((lane >> 4) << 4));
    uint32_t boffK = (uint32_t)((((lane >> 4) << 3) + (lane & 7)) * ROWB
                                + (((lane >> 3) & 1) << 4));
    uint32_t voff  = (uint32_t)(((((lane >> 3) & 1) << 3) + (lane & 7)) * ROWB
                                + ((lane >> 4) << 4));

    for (int i = 0; i < niter; i++) {
        int s = i & 1;
        if (i + 1 < niter) {
            load_kv(sb, s ^ 1, b, (i + 1) * 64, t);
            CPA_COMMIT();
            CPA_WAIT1();
        } else {
            CPA_WAIT0();
        }
        __syncthreads();
        uint32_t sK  = sb + STAGE0 + s * (4 * KT_B);
        uint32_t sV  = sK + 2 * KT_B;

        // ---- S = Q K^T (3-term fp16 split) ----
        float sacc[8][4];
#pragma unroll
        for (int f = 0; f < 8; f++)
#pragma unroll
            for (int q = 0; q < 4; q++) sacc[f][q] = 0.f;
#pragma unroll
        for (int ks = 0; ks < 8; ks++) {
            uint32_t qh[4], ql[4];
            ldm_x4(qh, sb + aoff + ks * 32);
            ldm_x4(ql, sb + QT_B + aoff + ks * 32);
#pragma unroll
            for (int nblk = 0; nblk < 4; nblk++) {
                uint32_t kh[4], kl[4];
                uint32_t ka = sK + nblk * (16 * ROWB) + boffK + ks * 32;
                ldm_x4(kh, ka);
                ldm_x4(kl, ka + KT_B);
                mma_f16(sacc[2 * nblk],     qh, kh);
                mma_f16(sacc[2 * nblk + 1], qh, kh + 2);
                mma_f16(sacc[2 * nblk],     qh, kl);
                mma_f16(sacc[2 * nblk + 1], qh, kl + 2);
                mma_f16(sacc[2 * nblk],     ql, kh);
                mma_f16(sacc[2 * nblk + 1], ql, kh + 2);
            }
        }

        // ---- online softmax on fragments ----
        int j0 = i * 64;
        bool need_mask = (j0 >= q0);
        float rm1 = -INFINITY, rm2 = -INFINITY;
#pragma unroll
        for (int f = 0; f < 8; f++) {
            int c0 = j0 + 8 * f + ((lane & 3) << 1);
            float s0 = sacc[f][0] * scale, s1 = sacc[f][1] * scale;
            float s2 = sacc[f][2] * scale, s3 = sacc[f][3] * scale;
            if (need_mask) {
                if (c0     > grow1) s0 = -INFINITY;
                if (c0 + 1 > grow1) s1 = -INFINITY;
                if (c0     > grow2) s2 = -INFINITY;
                if (c0 + 1 > grow2) s3 = -INFINITY;
            }
            sacc[f][0] = s0; sacc[f][1] = s1; sacc[f][2] = s2; sacc[f][3] = s3;
            rm1 = fmaxf(rm1, fmaxf(s0, s1));
            rm2 = fmaxf(rm2, fmaxf(s2, s3));
        }
        rm1 = fmaxf(rm1, __shfl_xor_sync(0xffffffffu, rm1, 1));
        rm1 = fmaxf(rm1, __shfl_xor_sync(0xffffffffu, rm1, 2));
        rm2 = fmaxf(rm2, __shfl_xor_sync(0xffffffffu, rm2, 1));
        rm2 = fmaxf(rm2, __shfl_xor_sync(0xffffffffu, rm2, 2));
        float mn1 = fmaxf(m1, rm1), mn2 = fmaxf(m2, rm2);
        float cor1 = __expf(m1 - mn1), cor2 = __expf(m2 - mn2);
        m1 = mn1; m2 = mn2;

        float rs1 = 0.f, rs2 = 0.f;
        uint32_t ph[8], ph2[8];
#pragma unroll
        for (int f = 0; f < 8; f++) {
            float p0 = __expf(sacc[f][0] - m1);
            float p1 = __expf(sacc[f][1] - m1);
            float p2 = __expf(sacc[f][2] - m2);
            float p3 = __expf(sacc[f][3] - m2);
            rs1 += p0 + p1; rs2 += p2 + p3;
            ph[f]  = packh2(p0, p1);
            ph2[f] = packh2(p2, p3);
        }
        rs1 += __shfl_xor_sync(0xffffffffu, rs1, 1);
        rs1 += __shfl_xor_sync(0xffffffffu, rs1, 2);
        rs2 += __shfl_xor_sync(0xffffffffu, rs2, 1);
        rs2 += __shfl_xor_sync(0xffffffffu, rs2, 2);
        l1 = l1 * cor1 + rs1;
        l2 = l2 * cor2 + rs2;
#pragma unroll
        for (int f = 0; f < 16; f++) {
            o[f][0] *= cor1; o[f][1] *= cor1;
            o[f][2] *= cor2; o[f][3] *= cor2;
        }

        // ---- O += P V (P fp16 from regs, V hi+lo) ----
#pragma unroll
        for (int kk = 0; kk < 4; kk++) {
            uint32_t a[4] = {ph[2 * kk], ph2[2 * kk], ph[2 * kk + 1], ph2[2 * kk + 1]};
#pragma unroll
            for (int dg = 0; dg < 8; dg++) {
                uint32_t vh[4], vl[4];
                uint32_t va = sV + kk * (16 * ROWB) + voff + dg * 32;
                ldm_x4_t(vh, va);
                ldm_x4_t(vl, va + KT_B);
                mma_f16(o[2 * dg],     a, vh);
                mma_f16(o[2 * dg + 1], a, vh + 2);
                mma_f16(o[2 * dg],     a, vl);
                mma_f16(o[2 * dg + 1], a, vl + 2);
            }
        }
        __syncthreads();
    }

    // epilogue: normalize + write [B, L, NH*HD]
    float inv1 = 1.f / l1, inv2 = 1.f / l2;
    float* o1 = out + ((size_t)(b * L + grow1)) * (NH * HD) + h * HD;
    float* o2 = out + ((size_t)(b * L + grow2)) * (NH * HD) + h * HD;
#pragma unroll
    for (int f = 0; f < 16; f++) {
        int d = 8 * f + ((lane & 3) << 1);
        *(float2*)(o1 + d) = make_float2(o[f][0] * inv1, o[f][1] * inv1);
        *(float2*)(o2 + d) = make_float2(o[f][2] * inv2, o[f][3] * inv2);
    }
}

// ---------------- launch --------------------------------------------------------
extern "C" void kernel_launch(void* const* d_in, const int* in_sizes, int n_in,
                              void* d_out, int out_size) {
    const float* x  = (const float*)d_in[0];
    const float* Wq = (const float*)d_in[1];
    const float* Wk = (const float*)d_in[2];
    const float* Wv = (const float*)d_in[3];
    float* out = (float*)d_out;

    (void)cudaFuncSetAttribute(qkv_gemm_kernel,
                               cudaFuncAttributeMaxDynamicSharedMemorySize, 81920);
    (void)cudaFuncSetAttribute(attn_kernel,
                               cudaFuncAttributeMaxDynamicSharedMemorySize, 208896);

    rope_table_kernel<<<512, 256>>>();
    xsplit_kernel<<<8192, 256>>>(x);
    wsplit_kernel<<<dim3(64, 72), 256>>>(Wq, Wk, Wv);
    qkv_gemm_kernel<<<dim3(18, 32), 256, 81920>>>();
    attn_kernel<<<dim3(16, NH, B), 256, 208896>>>(out);
}

// round 7
// speedup vs baseline: 4.7416x; 1.5515x over previous
#include <cuda_runtime.h>
#include <cuda_fp16.h>
#include <math.h>
#include <stdint.h>

#define B   2
#define L   2048
#define EMB 2048
#define NH  16
#define HD  128
#define NTOT 2304          // 2048 Q cols + 128 K + 128 V

// ---------------- scratch (device globals: no allocation allowed) -------------
__device__ __half g_Qh[2 * 16 * 2048 * 128];  // [B][NH][L][HD] RoPE'd fp16
__device__ __half g_Kh[2 * 2048 * 128];       // [B][L][HD] RoPE'd
__device__ __half g_Vh[2 * 2048 * 128];
__device__ float  g_Rc[2048 * 64];
__device__ float  g_Rs[2048 * 64];
__device__ __half g_Xh[4096 * 2048];          // X split hi
__device__ __half g_Xl[4096 * 2048];          // X split lo
__device__ __half g_Wth[NTOT * 2048];         // W^T fp16 [n][k]

// ---------------- PTX helpers ---------------------------------------------------
__device__ __forceinline__ uint32_t smem_u32(const void* p) {
    uint32_t a;
    asm("{ .reg .u64 t; cvta.to.shared.u64 t, %1; cvt.u32.u64 %0, t; }" : "=r"(a) : "l"(p));
    return a;
}
__device__ __forceinline__ void cpa16(uint32_t dst, const void* src) {
    asm volatile("cp.async.cg.shared.global [%0], [%1], 16;" :: "r"(dst), "l"(src));
}
#define CPA_COMMIT() asm volatile("cp.async.commit_group;" ::: "memory")
#define CPA_WAIT0()  asm volatile("cp.async.wait_group 0;" ::: "memory")
#define CPA_WAIT1()  asm volatile("cp.async.wait_group 1;" ::: "memory")

__device__ __forceinline__ void ldm_x4(uint32_t* r, uint32_t addr) {
    asm volatile("ldmatrix.sync.aligned.m8n8.x4.shared.b16 {%0,%1,%2,%3}, [%4];"
        : "=r"(r[0]), "=r"(r[1]), "=r"(r[2]), "=r"(r[3]) : "r"(addr));
}
__device__ __forceinline__ void ldm_x4_t(uint32_t* r, uint32_t addr) {
    asm volatile("ldmatrix.sync.aligned.m8n8.x4.trans.shared.b16 {%0,%1,%2,%3}, [%4];"
        : "=r"(r[0]), "=r"(r[1]), "=r"(r[2]), "=r"(r[3]) : "r"(addr));
}
__device__ __forceinline__ void mma_f16(float* c, const uint32_t* a, const uint32_t* b) {
    asm volatile("mma.sync.aligned.m16n8k16.row.col.f32.f16.f16.f32 "
        "{%0,%1,%2,%3}, {%4,%5,%6,%7}, {%8,%9}, {%0,%1,%2,%3};"
        : "+f"(c[0]), "+f"(c[1]), "+f"(c[2]), "+f"(c[3])
        : "r"(a[0]), "r"(a[1]), "r"(a[2]), "r"(a[3]), "r"(b[0]), "r"(b[1]));
}
__device__ __forceinline__ uint32_t packh2(float a, float b) {
    __half2 h = __floats2half2_rn(a, b);
    return *(uint32_t*)&h;
}

// ---------------- RoPE tables ----------------------------------------------------
__global__ void rope_table_kernel() {
    int idx = blockIdx.x * blockDim.x + threadIdx.x;
    int l = idx >> 6;
    int i = idx & 63;
    double invf = pow(10000.0, -(double)(2 * i) / (double)HD);
    double a = (double)l * invf;
    g_Rc[idx] = (float)cos(a);
    g_Rs[idx] = (float)sin(a);
}

// ---------------- X hi/lo fp16 split --------------------------------------------
__global__ void xsplit_kernel(const float* __restrict__ X) {
    int i = (blockIdx.x * 256 + threadIdx.x) * 4;
    float4 v = *(const float4*)(X + i);
    float vv[4] = {v.x, v.y, v.z, v.w};
    __half h[4], lo[4];
#pragma unroll
    for (int j = 0; j < 4; j++) {
        h[j]  = __float2half_rn(vv[j]);
        lo[j] = __float2half_rn(vv[j] - __half2float(h[j]));
    }
    *(uint2*)(g_Xh + i) = *(uint2*)h;
    *(uint2*)(g_Xl + i) = *(uint2*)lo;
}

// ---------------- W transpose + fp16 ---------------------------------------------
__global__ void wsplit_kernel(const float* __restrict__ Wq,
                              const float* __restrict__ Wk,
                              const float* __restrict__ Wv) {
    __shared__ float tile[32][33];
    int kb = blockIdx.x * 32;
    int nb = blockIdx.y * 32;
    const float* W; int ldw, n0;
    if (nb < 2048)      { W = Wq; ldw = 2048; n0 = nb; }
    else if (nb < 2176) { W = Wk; ldw = 128;  n0 = nb - 2048; }
    else                { W = Wv; ldw = 128;  n0 = nb - 2176; }
    int tx = threadIdx.x & 31, ty = threadIdx.x >> 5;
#pragma unroll
    for (int r = 0; r < 32; r += 8)
        tile[ty + r][tx] = W[(size_t)(kb + ty + r) * ldw + n0 + tx];
    __syncthreads();
#pragma unroll
    for (int r = 0; r < 32; r += 8)
        g_Wth[(size_t)(nb + ty + r) * 2048 + kb + tx] =
            __float2half_rn(tile[tx][ty + r]);
}

// ---------------- QKV GEMM: 2-term split-fp16 mma.sync, RoPE epilogue -----------
// Grid (18, 32), 256 thr = 8 warps (4m x 2n). Tile 128x128, BK=32.
// smem/stage: Xh | Xl | Wh tiles, 10240B each; 2 stages = 61440B.
#define TS      80
#define TILE_B  (128 * TS)
#define STG_B   (3 * TILE_B)
#define NCHUNK  64

__device__ __forceinline__ void load_chunk(uint32_t sbase, int stage,
                                           int m0, int n0, int kc, int t) {
    uint32_t sb = sbase + stage * STG_B;
#pragma unroll
    for (int it = 0; it < 6; it++) {
        int g = t + 256 * it;               // 0..1535
        int tile = g >> 9;
        int r = (g >> 2) & 127;
        int c = g & 3;
        uint32_t dst = sb + tile * TILE_B + r * TS + c * 16;
        const __half* src;
        if (tile == 0)      src = g_Xh  + (size_t)(m0 + r) * EMB + kc + c * 8;
        else if (tile == 1) src = g_Xl  + (size_t)(m0 + r) * EMB + kc + c * 8;
        else                src = g_Wth + (size_t)(n0 + r) * EMB + kc + c * 8;
        cpa16(dst, src);
    }
}

__global__ __launch_bounds__(256, 2) void qkv_gemm_kernel() {
    extern __shared__ char smem[];
    uint32_t sbase = smem_u32(smem);
    int t = threadIdx.x;
    int lane = t & 31, w = t >> 5;
    int wm = w & 3, wn = w >> 2;
    int nb = blockIdx.x;
    int m0 = blockIdx.y * 128;
    int n0 = nb * 128;

    float acc[2][8][4];
#pragma unroll
    for (int i = 0; i < 2; i++)
#pragma unroll
        for (int j = 0; j < 8; j++)
#pragma unroll
            for (int q = 0; q < 4; q++) acc[i][j][q] = 0.f;

    int aRow = wm * 32 + (lane & 15);
    uint32_t aOff = (uint32_t)(aRow * TS + ((lane >> 4) << 4));
    int bRow = wn * 64 + ((lane >> 4) << 3) + (lane & 7);
    uint32_t bOff = (uint32_t)(bRow * TS + (((lane >> 3) & 1) << 4));

    load_chunk(sbase, 0, m0, n0, 0, t);
    CPA_COMMIT();

    for (int i = 0; i < NCHUNK; i++) {
        int s = i & 1;
        if (i + 1 < NCHUNK) {
            load_chunk(sbase, s ^ 1, m0, n0, (i + 1) * 32, t);
            CPA_COMMIT();
            CPA_WAIT1();
        } else {
            CPA_WAIT0();
        }
        __syncthreads();

        uint32_t sb = sbase + s * STG_B;
#pragma unroll
        for (int ks = 0; ks < 2; ks++) {
            uint32_t kb = ks * 32;
            uint32_t ah[2][4], al[2][4];
#pragma unroll
            for (int mf = 0; mf < 2; mf++) {
                ldm_x4(ah[mf], sb + aOff + (uint32_t)(mf * 16 * TS) + kb);
                ldm_x4(al[mf], sb + TILE_B + aOff + (uint32_t)(mf * 16 * TS) + kb);
            }
#pragma unroll
            for (int ng = 0; ng < 4; ng++) {
                uint32_t bh[4];
                ldm_x4(bh, sb + 2 * TILE_B + bOff + (uint32_t)(ng * 16 * TS) + kb);
#pragma unroll
                for (int sub = 0; sub < 2; sub++) {
                    int nf = ng * 2 + sub;
                    mma_f16(acc[0][nf], ah[0], bh + 2 * sub);
                    mma_f16(acc[1][nf], ah[1], bh + 2 * sub);
                    mma_f16(acc[0][nf], al[0], bh + 2 * sub);
                    mma_f16(acc[1][nf], al[1], bh + 2 * sub);
                }
            }
        }
        __syncthreads();
    }

    // epilogue: RoPE (Q,K) + fp16 scatter
#pragma unroll
    for (int mf = 0; mf < 2; mf++) {
#pragma unroll
        for (int half = 0; half < 2; half++) {
            int row = m0 + wm * 32 + mf * 16 + (lane >> 2) + half * 8;
            int bb = row >> 11;
            int l  = row & 2047;
#pragma unroll
            for (int nf = 0; nf < 8; nf++) {
                int dcol = wn * 64 + nf * 8 + ((lane & 3) << 1);
                float e = acc[mf][nf][half * 2 + 0];
                float o = acc[mf][nf][half * 2 + 1];
                float2 v;
                if (nb != 17) {
                    float c  = g_Rc[l * 64 + (dcol >> 1)];
                    float sn = g_Rs[l * 64 + (dcol >> 1)];
                    v.x = e * c - o * sn;
                    v.y = o * c + e * sn;
                } else {
                    v.x = e; v.y = o;
                }
                __half2 hp = __floats2half2_rn(v.x, v.y);
                if (nb < 16)
                    *(__half2*)(g_Qh + ((size_t)(bb * NH + nb) * L + l) * HD + dcol) = hp;
                else if (nb == 16)
                    *(__half2*)(g_Kh + (size_t)row * HD + dcol) = hp;
                else
                    *(__half2*)(g_Vh + (size_t)row * HD + dcol) = hp;
            }
        }
    }
}

// ---------------- causal flash attention: fp16 mma.sync, 2 CTA/SM ---------------
// Grid (16 qtiles LPT-remapped, 16 h, 2 b), 256 thr = 8 warps (16 q-rows each).
// smem: Q (128x272) + 2 KV stages (Kh|Vh 64x272 each) = 104448 B -> 2 CTAs/SM.
#define ROWB 272
#define QT_B 34816
#define KT_B 17408
#define STAGE0 34816

__device__ __forceinline__ void load_kv(uint32_t sb, int stage, int b, int j0, int t) {
    uint32_t base = sb + STAGE0 + stage * (2 * KT_B);
#pragma unroll
    for (int it = 0; it < 8; it++) {
        int g = t + 256 * it;             // 0..2047
        int tile = g >> 10;               // K, V
        int r = (g >> 4) & 63;
        int c = g & 15;
        size_t off = (size_t)(b * L + j0 + r) * HD + c * 8;
        const __half* src = (tile ? g_Vh : g_Kh) + off;
        cpa16(base + tile * KT_B + r * ROWB + c * 16, src);
    }
}

__global__ __launch_bounds__(256, 2) void attn_kernel(float* __restrict__ out) {
    extern __shared__ char sm[];
    uint32_t sb = smem_u32(sm);
    int t = threadIdx.x;
    int lane = t & 31, wq = t >> 5;
    int qt = 15 - blockIdx.x;              // LPT: heavy diagonal tiles first
    int h = blockIdx.y, b = blockIdx.z;
    int q0 = qt * 128;

    {
        const __half* Qp = g_Qh + ((size_t)(b * NH + h) * L + q0) * HD;
#pragma unroll
        for (int it = 0; it < 8; it++) {
            int g = t + 256 * it;          // 0..2047
            int r = g >> 4;
            int c = g & 15;
            cpa16(sb + r * ROWB + c * 16, Qp + (size_t)r * HD + c * 8);
        }
    }
    load_kv(sb, 0, b, 0, t);
    CPA_COMMIT();

    float o[16][4];
#pragma unroll
    for (int i = 0; i < 16; i++)
#pragma unroll
        for (int j = 0; j < 4; j++) o[i][j] = 0.f;
    float m1 = -INFINITY, m2 = -INFINITY, l1 = 0.f, l2 = 0.f;

    const float scale = 0.08838834764831845f;
    int niter = 2 * qt + 2;
    int grow1 = q0 + wq * 16 + (lane >> 2);
    int grow2 = grow1 + 8;

    uint32_t aoff  = (uint32_t)((wq * 16 + (lane & 15)) * ROWB + ((lane >> 4) << 4));
    uint32_t boffK = (uint32_t)((((lane >> 4) << 3) + (lane & 7)) * ROWB
                                + (((lane >> 3) & 1) << 4));
    uint32_t voff  = (uint32_t)(((((lane >> 3) & 1) << 3) + (lane & 7)) * ROWB
                                + ((lane >> 4) << 4));

    for (int i = 0; i < niter; i++) {
        int s = i & 1;
        if (i + 1 < niter) {
            load_kv(sb, s ^ 1, b, (i + 1) * 64, t);
            CPA_COMMIT();
            CPA_WAIT1();
        } else {
            CPA_WAIT0();
        }
        __syncthreads();
        uint32_t sK = sb + STAGE0 + s * (2 * KT_B);
        uint32_t sV = sK + KT_B;

        // ---- S = Q K^T ----
        float sacc[8][4];
#pragma unroll
        for (int f = 0; f < 8; f++)
#pragma unroll
            for (int q = 0; q < 4; q++) sacc[f][q] = 0.f;
#pragma unroll
        for (int ks = 0; ks < 8; ks++) {
            uint32_t qh[4];
            ldm_x4(qh, sb + aoff + ks * 32);
#pragma unroll
            for (int nblk = 0; nblk < 4; nblk++) {
                uint32_t kh[4];
                ldm_x4(kh, sK + nblk * (16 * ROWB) + boffK + ks * 32);
                mma_f16(sacc[2 * nblk],     qh, kh);
                mma_f16(sacc[2 * nblk + 1], qh, kh + 2);
            }
        }

        // ---- online softmax on fragments ----
        int j0 = i * 64;
        bool need_mask = (j0 >= q0);
        float rm1 = -INFINITY, rm2 = -INFINITY;
#pragma unroll
        for (int f = 0; f < 8; f++) {
            int c0 = j0 + 8 * f + ((lane & 3) << 1);
            float s0 = sacc[f][0] * scale, s1 = sacc[f][1] * scale;
            float s2 = sacc[f][2] * scale, s3 = sacc[f][3] * scale;
            if (need_mask) {
                if (c0     > grow1) s0 = -INFINITY;
                if (c0 + 1 > grow1) s1 = -INFINITY;
                if (c0     > grow2) s2 = -INFINITY;
                if (c0 + 1 > grow2) s3 = -INFINITY;
            }
            sacc[f][0] = s0; sacc[f][1] = s1; sacc[f][2] = s2; sacc[f][3] = s3;
            rm1 = fmaxf(rm1, fmaxf(s0, s1));
            rm2 = fmaxf(rm2, fmaxf(s2, s3));
        }
        rm1 = fmaxf(rm1, __shfl_xor_sync(0xffffffffu, rm1, 1));
        rm1 = fmaxf(rm1, __shfl_xor_sync(0xffffffffu, rm1, 2));
        rm2 = fmaxf(rm2, __shfl_xor_sync(0xffffffffu, rm2, 1));
        rm2 = fmaxf(rm2, __shfl_xor_sync(0xffffffffu, rm2, 2));
        float mn1 = fmaxf(m1, rm1), mn2 = fmaxf(m2, rm2);
        float cor1 = __expf(m1 - mn1), cor2 = __expf(m2 - mn2);
        m1 = mn1; m2 = mn2;

        float rs1 = 0.f, rs2 = 0.f;
        uint32_t ph[8], ph2[8];
#pragma unroll
        for (int f = 0; f < 8; f++) {
            float p0 = __expf(sacc[f][0] - m1);
            float p1 = __expf(sacc[f][1] - m1);
            float p2 = __expf(sacc[f][2] - m2);
            float p3 = __expf(sacc[f][3] - m2);
            rs1 += p0 + p1; rs2 += p2 + p3;
            ph[f]  = packh2(p0, p1);
            ph2[f] = packh2(p2, p3);
        }
        rs1 += __shfl_xor_sync(0xffffffffu, rs1, 1);
        rs1 += __shfl_xor_sync(0xffffffffu, rs1, 2);
        rs2 += __shfl_xor_sync(0xffffffffu, rs2, 1);
        rs2 += __shfl_xor_sync(0xffffffffu, rs2, 2);
        l1 = l1 * cor1 + rs1;
        l2 = l2 * cor2 + rs2;
#pragma unroll
        for (int f = 0; f < 16; f++) {
            o[f][0] *= cor1; o[f][1] *= cor1;
            o[f][2] *= cor2; o[f][3] *= cor2;
        }

        // ---- O += P V ----
#pragma unroll
        for (int kk = 0; kk < 4; kk++) {
            uint32_t a[4] = {ph[2 * kk], ph2[2 * kk], ph[2 * kk + 1], ph2[2 * kk + 1]};
#pragma unroll
            for (int dg = 0; dg < 8; dg++) {
                uint32_t vh[4];
                ldm_x4_t(vh, sV + kk * (16 * ROWB) + voff + dg * 32);
                mma_f16(o[2 * dg],     a, vh);
                mma_f16(o[2 * dg + 1], a, vh + 2);
            }
        }
        __syncthreads();
    }

    // epilogue
    float inv1 = 1.f / l1, inv2 = 1.f / l2;
    float* o1 = out + ((size_t)(b * L + grow1)) * (NH * HD) + h * HD;
    float* o2 = out + ((size_t)(b * L + grow2)) * (NH * HD) + h * HD;
#pragma unroll
    for (int f = 0; f < 16; f++) {
        int d = 8 * f + ((lane & 3) << 1);
        *(float2*)(o1 + d) = make_float2(o[f][0] * inv1, o[f][1] * inv1);
        *(float2*)(o2 + d) = make_float2(o[f][2] * inv2, o[f][3] * inv2);
    }
}

// ---------------- launch --------------------------------------------------------
extern "C" void kernel_launch(void* const* d_in, const int* in_sizes, int n_in,
                              void* d_out, int out_size) {
    const float* x  = (const float*)d_in[0];
    const float* Wq = (const float*)d_in[1];
    const float* Wk = (const float*)d_in[2];
    const float* Wv = (const float*)d_in[3];
    float* out = (float*)d_out;

    (void)cudaFuncSetAttribute(qkv_gemm_kernel,
                               cudaFuncAttributeMaxDynamicSharedMemorySize, 61440);
    (void)cudaFuncSetAttribute(attn_kernel,
                               cudaFuncAttributeMaxDynamicSharedMemorySize, 104448);

    rope_table_kernel<<<512, 256>>>();
    xsplit_kernel<<<8192, 256>>>(x);
    wsplit_kernel<<<dim3(64, 72), 256>>>(Wq, Wk, Wv);
    qkv_gemm_kernel<<<dim3(18, 32), 256, 61440>>>();
    attn_kernel<<<dim3(16, NH, B), 256, 104448>>>(out);
}